// round 4
// baseline (speedup 1.0000x reference)
#include <cuda_runtime.h>
#include <cuda_bf16.h>

// Problem constants (fixed by the dataset)
#define NN      50000      // nodes
#define EE      600000     // edges
#define DIM     128        // input/hidden dim
#define HC      256        // H*C
#define NCOLS   512        // 2*H*C (x_l | x_r)
#define NEG     0.2f
#define RMS_EPS 1e-6f

#define SCAN_BPB 2048      // elements per scan block
#define NBLK_SCAN ((NN + SCAN_BPB - 1) / SCAN_BPB)   // 25

// ---------------- scratch (static device allocations) ----------------
__device__ float g_scale[NN];                       // rms row scale
__device__ float g_wcat[DIM * NCOLS];               // rmsw-folded [W_l | W_r]
__device__ float g_xcat[(size_t)NN * NCOLS];        // per node: [x_l(256) | x_r(256)]
__device__ int   g_deg[NN];                         // in-degree
__device__ int   g_cursor[NN];                      // fill cursors
__device__ int   g_rowptr[NN + 1];                  // CSR row pointers (by dst)
__device__ int   g_bsum[NBLK_SCAN];                 // scan block sums
__device__ int   g_boff[NBLK_SCAN];                 // scan block offsets
__device__ int   g_csrsrc[EE];                      // src ids sorted by dst

// ---------------- helpers ----------------
__device__ __forceinline__ float warp_sum(float v) {
    #pragma unroll
    for (int off = 16; off; off >>= 1) v += __shfl_down_sync(0xffffffffu, v, off);
    return v;
}

// ---------------- K0: init (zero deg + cursor) ----------------
__global__ void k_init() {
    int idx = blockIdx.x * blockDim.x + threadIdx.x;
    int stride = gridDim.x * blockDim.x;
    for (int i = idx; i < NN; i += stride) { g_deg[i] = 0; g_cursor[i] = 0; }
}

// ---------------- K1: per-row RMS scale ----------------
__global__ __launch_bounds__(256) void k_scale(const float* __restrict__ x) {
    int warp = (blockIdx.x * blockDim.x + threadIdx.x) >> 5;
    int lane = threadIdx.x & 31;
    if (warp >= NN) return;
    const float4* xr = (const float4*)(x + (size_t)warp * DIM);
    float4 v = xr[lane];
    float s = v.x * v.x + v.y * v.y + v.z * v.z + v.w * v.w;
    s = warp_sum(s);
    s = __shfl_sync(0xffffffffu, s, 0);
    if (lane == 0) g_scale[warp] = rsqrtf(s * (1.0f / DIM) + RMS_EPS);
}

// ---------------- K2: fold rms_weight into [W_l | W_r] ----------------
__global__ void k_fold(const float* __restrict__ rmsw,
                       const float* __restrict__ wl,
                       const float* __restrict__ wr) {
    int idx = blockIdx.x * blockDim.x + threadIdx.x;   // over DIM*NCOLS
    if (idx >= DIM * NCOLS) return;
    int k = idx / NCOLS, j = idx % NCOLS;
    float w = (j < HC) ? wl[k * HC + j] : wr[k * HC + (j - HC)];
    g_wcat[idx] = rmsw[k] * w;
}

// ---------------- K3: GEMM  xcat = (x*scale) @ wcat  (fp32) ----------------
// BM=128, BN=128, BK=16, 256 threads, 8x8 microtile, double-buffered smem,
// ONE __syncthreads per K-tile (8 total). Global loads issued before compute.
__global__ __launch_bounds__(256, 2) void k_gemm(const float* __restrict__ x) {
    __shared__ float As[2][16][128];   // transposed: [k][m]
    __shared__ float Bs[2][16][128];

    const int t  = threadIdx.x;
    const int n0 = blockIdx.x * 128;
    const int m0 = blockIdx.y * 128;
    const int tx = t & 15;
    const int ty = t >> 4;

    float acc[8][8];
    #pragma unroll
    for (int i = 0; i < 8; i++)
        #pragma unroll
        for (int j = 0; j < 8; j++) acc[i][j] = 0.0f;

    // A loader: 128 rows x 16 k = 512 float4 slots; slot s -> row s>>2, kq (s&3)*4
    const int as0 = t, as1 = t + 256;
    const int ar0 = as0 >> 2, ak0 = (as0 & 3) << 2;
    const int ar1 = as1 >> 2, ak1 = (as1 & 3) << 2;
    const int arow0 = m0 + ar0, arow1 = m0 + ar1;
    const float asc0 = (arow0 < NN) ? g_scale[arow0] : 0.0f;
    const float asc1 = (arow1 < NN) ? g_scale[arow1] : 0.0f;
    const float* ap0 = x + (size_t)arow0 * DIM + ak0;
    const float* ap1 = x + (size_t)arow1 * DIM + ak1;

    // B loader: 16 k x 128 cols = 512 float4 slots; slot s -> k s>>5, col (s&31)*4
    const int bk0 = as0 >> 5, bc0 = (as0 & 31) << 2;
    const int bk1 = as1 >> 5, bc1 = (as1 & 31) << 2;
    const float* bp0 = g_wcat + (size_t)bk0 * NCOLS + n0 + bc0;
    const float* bp1 = g_wcat + (size_t)bk1 * NCOLS + n0 + bc1;

    float4 av0, av1, bv0, bv1;
    const float4 z4 = make_float4(0.f, 0.f, 0.f, 0.f);

    // prologue: tile 0 -> buf 0
    av0 = (arow0 < NN) ? *(const float4*)(ap0) : z4;
    av1 = (arow1 < NN) ? *(const float4*)(ap1) : z4;
    bv0 = *(const float4*)(bp0);
    bv1 = *(const float4*)(bp1);
    As[0][ak0 + 0][ar0] = av0.x * asc0;
    As[0][ak0 + 1][ar0] = av0.y * asc0;
    As[0][ak0 + 2][ar0] = av0.z * asc0;
    As[0][ak0 + 3][ar0] = av0.w * asc0;
    As[0][ak1 + 0][ar1] = av1.x * asc1;
    As[0][ak1 + 1][ar1] = av1.y * asc1;
    As[0][ak1 + 2][ar1] = av1.z * asc1;
    As[0][ak1 + 3][ar1] = av1.w * asc1;
    *(float4*)&Bs[0][bk0][bc0] = bv0;
    *(float4*)&Bs[0][bk1][bc1] = bv1;
    __syncthreads();

    const int NT = DIM / 16;   // 8 tiles
    #pragma unroll
    for (int it = 0; it < NT; it++) {
        const int buf = it & 1;
        const bool more = (it + 1) < NT;
        if (more) {
            const int kc = (it + 1) * 16;
            av0 = (arow0 < NN) ? *(const float4*)(ap0 + kc) : z4;
            av1 = (arow1 < NN) ? *(const float4*)(ap1 + kc) : z4;
            bv0 = *(const float4*)(bp0 + (size_t)kc * NCOLS);
            bv1 = *(const float4*)(bp1 + (size_t)kc * NCOLS);
        }

        #pragma unroll
        for (int k = 0; k < 16; k++) {
            float4 a0 = *(const float4*)&As[buf][k][ty << 3];
            float4 a1 = *(const float4*)&As[buf][k][(ty << 3) + 4];
            float4 b0 = *(const float4*)&Bs[buf][k][tx << 3];
            float4 b1 = *(const float4*)&Bs[buf][k][(tx << 3) + 4];
            float a[8] = {a0.x, a0.y, a0.z, a0.w, a1.x, a1.y, a1.z, a1.w};
            float b[8] = {b0.x, b0.y, b0.z, b0.w, b1.x, b1.y, b1.z, b1.w};
            #pragma unroll
            for (int i = 0; i < 8; i++)
                #pragma unroll
                for (int j = 0; j < 8; j++)
                    acc[i][j] += a[i] * b[j];
        }

        if (more) {
            const int nb = buf ^ 1;
            As[nb][ak0 + 0][ar0] = av0.x * asc0;
            As[nb][ak0 + 1][ar0] = av0.y * asc0;
            As[nb][ak0 + 2][ar0] = av0.z * asc0;
            As[nb][ak0 + 3][ar0] = av0.w * asc0;
            As[nb][ak1 + 0][ar1] = av1.x * asc1;
            As[nb][ak1 + 1][ar1] = av1.y * asc1;
            As[nb][ak1 + 2][ar1] = av1.z * asc1;
            As[nb][ak1 + 3][ar1] = av1.w * asc1;
            *(float4*)&Bs[nb][bk0][bc0] = bv0;
            *(float4*)&Bs[nb][bk1][bc1] = bv1;
        }
        __syncthreads();
    }

    #pragma unroll
    for (int i = 0; i < 8; i++) {
        int row = m0 + (ty << 3) + i;
        if (row < NN) {
            float* o = g_xcat + (size_t)row * NCOLS + n0 + (tx << 3);
            *(float4*)(o + 0) = make_float4(acc[i][0], acc[i][1], acc[i][2], acc[i][3]);
            *(float4*)(o + 4) = make_float4(acc[i][4], acc[i][5], acc[i][6], acc[i][7]);
        }
    }
}

// ---------------- K4: degree histogram ----------------
__global__ void k_hist(const int* __restrict__ ei) {
    int e = blockIdx.x * blockDim.x + threadIdx.x;
    if (e >= EE) return;
    atomicAdd(&g_deg[ei[EE + e]], 1);
}

// ---------------- K5a: per-block exclusive scan ----------------
__global__ __launch_bounds__(256) void k_scan_block() {
    __shared__ int ssum[256];
    int base  = blockIdx.x * SCAN_BPB;
    int tbase = base + threadIdx.x * 8;
    int local[8];
    int run = 0;
    #pragma unroll
    for (int i = 0; i < 8; i++) {
        int v = (tbase + i < NN) ? g_deg[tbase + i] : 0;
        local[i] = run;
        run += v;
    }
    int myrun = run;
    ssum[threadIdx.x] = run;
    __syncthreads();
    #pragma unroll
    for (int off = 1; off < 256; off <<= 1) {
        int v = (threadIdx.x >= off) ? ssum[threadIdx.x - off] : 0;
        __syncthreads();
        ssum[threadIdx.x] += v;
        __syncthreads();
    }
    int excl = ssum[threadIdx.x] - myrun;
    #pragma unroll
    for (int i = 0; i < 8; i++)
        if (tbase + i < NN) g_rowptr[tbase + i] = excl + local[i];
    if (threadIdx.x == 255) g_bsum[blockIdx.x] = ssum[255];
}

// ---------------- K5b: scan block sums (tiny) ----------------
__global__ void k_scan_top() {
    if (threadIdx.x == 0) {
        int run = 0;
        for (int b = 0; b < NBLK_SCAN; b++) {
            int v = g_bsum[b];
            g_boff[b] = run;
            run += v;
        }
    }
}

// ---------------- K5c: add block offsets ----------------
__global__ void k_scan_add() {
    int idx = blockIdx.x * blockDim.x + threadIdx.x;
    if (idx < NN) g_rowptr[idx] += g_boff[idx / SCAN_BPB];
    if (idx == 0) g_rowptr[NN] = EE;
}

// ---------------- K6: fill CSR (src ids grouped by dst) ----------------
__global__ void k_fill(const int* __restrict__ ei) {
    int e = blockIdx.x * blockDim.x + threadIdx.x;
    if (e >= EE) return;
    int dst = ei[EE + e];
    int pos = g_rowptr[dst] + atomicAdd(&g_cursor[dst], 1);
    g_csrsrc[pos] = ei[e];
}

// ---------------- K7: fused edge pass (online softmax + aggregate) ----------------
// One warp per destination node. No atomics anywhere.
__global__ __launch_bounds__(256) void k_edge(const float* __restrict__ att,
                                              float* __restrict__ out) {
    int node = (blockIdx.x * blockDim.x + threadIdx.x) >> 5;
    int lane = threadIdx.x & 31;
    if (node >= NN) return;

    const float4* a4 = (const float4*)att;
    float4 t0 = __ldg(&a4[lane]);          // att head 0, cols [lane*4,+4)
    float4 t1 = __ldg(&a4[lane + 32]);     // att head 1

    const float4* xr = (const float4*)(g_xcat + (size_t)node * NCOLS + HC);
    float4 r0 = xr[lane];
    float4 r1 = xr[lane + 32];

    float m0 = -__int_as_float(0x7f800000), m1 = m0;   // -inf
    float s0 = 0.f, s1 = 0.f;
    float4 A0 = make_float4(0.f, 0.f, 0.f, 0.f);
    float4 A1 = make_float4(0.f, 0.f, 0.f, 0.f);

    int beg = g_rowptr[node];
    int end = g_rowptr[node + 1];

    for (int j = beg; j < end; j++) {
        int src = g_csrsrc[j];
        const float4* xl = (const float4*)(g_xcat + (size_t)src * NCOLS);
        float4 l0 = xl[lane];
        float4 l1 = xl[lane + 32];

        float v, p0 = 0.f, p1 = 0.f;
        v = l0.x + r0.x; p0 += (v > 0.f ? v : NEG * v) * t0.x;
        v = l0.y + r0.y; p0 += (v > 0.f ? v : NEG * v) * t0.y;
        v = l0.z + r0.z; p0 += (v > 0.f ? v : NEG * v) * t0.z;
        v = l0.w + r0.w; p0 += (v > 0.f ? v : NEG * v) * t0.w;
        v = l1.x + r1.x; p1 += (v > 0.f ? v : NEG * v) * t1.x;
        v = l1.y + r1.y; p1 += (v > 0.f ? v : NEG * v) * t1.y;
        v = l1.z + r1.z; p1 += (v > 0.f ? v : NEG * v) * t1.z;
        v = l1.w + r1.w; p1 += (v > 0.f ? v : NEG * v) * t1.w;

        // butterfly reduce — all lanes end with the full logits
        #pragma unroll
        for (int off = 16; off; off >>= 1) {
            p0 += __shfl_xor_sync(0xffffffffu, p0, off);
            p1 += __shfl_xor_sync(0xffffffffu, p1, off);
        }

        // online softmax update, head 0
        float nm0 = fmaxf(m0, p0);
        float c0  = __expf(m0 - nm0);   // 0 on first edge (m0 = -inf, nm0 finite)
        float w0  = __expf(p0 - nm0);
        s0 = s0 * c0 + w0;
        A0.x = A0.x * c0 + w0 * l0.x;
        A0.y = A0.y * c0 + w0 * l0.y;
        A0.z = A0.z * c0 + w0 * l0.z;
        A0.w = A0.w * c0 + w0 * l0.w;
        m0 = nm0;
        // head 1
        float nm1 = fmaxf(m1, p1);
        float c1  = __expf(m1 - nm1);
        float w1  = __expf(p1 - nm1);
        s1 = s1 * c1 + w1;
        A1.x = A1.x * c1 + w1 * l1.x;
        A1.y = A1.y * c1 + w1 * l1.y;
        A1.z = A1.z * c1 + w1 * l1.z;
        A1.w = A1.w * c1 + w1 * l1.w;
        m1 = nm1;
    }

    float i0 = 0.5f / (s0 + 1e-16f);
    float i1 = 0.5f / (s1 + 1e-16f);
    float4 o;
    o.x = A0.x * i0 + A1.x * i1;
    o.y = A0.y * i0 + A1.y * i1;
    o.z = A0.z * i0 + A1.z * i1;
    o.w = A0.w * i0 + A1.w * i1;
    *(float4*)(out + (size_t)node * DIM + (lane << 2)) = o;
}

// ---------------- launch ----------------
extern "C" void kernel_launch(void* const* d_in, const int* in_sizes, int n_in,
                              void* d_out, int out_size) {
    const float* x    = (const float*)d_in[0];
    const int*   ei   = (const int*)d_in[1];
    const float* rmsw = (const float*)d_in[2];
    const float* wl   = (const float*)d_in[3];
    const float* wr   = (const float*)d_in[4];
    const float* att  = (const float*)d_in[5];
    float* out = (float*)d_out;

    k_init<<<256, 256>>>();
    k_scale<<<(NN * 32 + 255) / 256, 256>>>(x);
    k_fold<<<(DIM * NCOLS + 255) / 256, 256>>>(rmsw, wl, wr);
    {
        dim3 grid(NCOLS / 128, (NN + 127) / 128);
        k_gemm<<<grid, 256>>>(x);
    }
    k_hist<<<(EE + 255) / 256, 256>>>(ei);
    k_scan_block<<<NBLK_SCAN, 256>>>();
    k_scan_top<<<1, 32>>>();
    k_scan_add<<<(NN + 255) / 256, 256>>>();
    k_fill<<<(EE + 255) / 256, 256>>>(ei);
    k_edge<<<(NN * 32 + 255) / 256, 256>>>(att, out);
}